// round 4
// baseline (speedup 1.0000x reference)
#include <cuda_runtime.h>
#include <cuda_bf16.h>
#include <cstdint>

#define FDIM 128

// per-node precomputed A = x@W1a (gathered by idx_i), B = x@W1b (by idx_j)
__device__ float g_A[50000 * FDIM];
__device__ float g_B[50000 * FDIM];
// bf16 hi/lo swizzled images of W1a^T, W1b^T, W1c^T : [part][hi/lo][32KB]
__device__ __align__(16) unsigned g_img[3][2][8192];
// silu quadratic table: 256 bins over [-8,8], (c0,c1,c2,0)
__device__ float4 g_tab[256];

// ---------------------------------------------------------------------------
// helpers
// ---------------------------------------------------------------------------
__device__ __forceinline__ uint32_t smem_u32(const void* p) {
    uint32_t a;
    asm("{ .reg .u64 t; cvta.to.shared.u64 t, %1; cvt.u32.u64 %0, t; }"
        : "=r"(a) : "l"(p));
    return a;
}
__device__ __forceinline__ void ldsm_x4(uint32_t& a0, uint32_t& a1,
                                        uint32_t& a2, uint32_t& a3, uint32_t addr) {
    asm volatile("ldmatrix.sync.aligned.m8n8.x4.shared.b16 {%0,%1,%2,%3}, [%4];"
                 : "=r"(a0), "=r"(a1), "=r"(a2), "=r"(a3) : "r"(addr));
}
__device__ __forceinline__ void mma_bf16(float* d, const uint32_t* a,
                                         uint32_t b0, uint32_t b1) {
    asm volatile("mma.sync.aligned.m16n8k16.row.col.f32.bf16.bf16.f32 "
                 "{%0,%1,%2,%3}, {%4,%5,%6,%7}, {%8,%9}, {%0,%1,%2,%3};"
                 : "+f"(d[0]), "+f"(d[1]), "+f"(d[2]), "+f"(d[3])
                 : "r"(a[0]), "r"(a[1]), "r"(a[2]), "r"(a[3]), "r"(b0), "r"(b1));
}
// swizzled byte offset in a [rows x 128] bf16 tile (row stride 256B,
// 16B chunks XOR-permuted by row&7 -> conflict-free ldmatrix)
__device__ __forceinline__ uint32_t sw(int row, int chunk16) {
    return (uint32_t)(row * 256 + ((chunk16 ^ (row & 7)) << 4));
}
__device__ __forceinline__ uint32_t pack_bf16(__nv_bfloat16 lo, __nv_bfloat16 hi) {
    return ((uint32_t)__bfloat16_as_ushort(hi) << 16) | __bfloat16_as_ushort(lo);
}
__device__ __forceinline__ void cvt_store4(char* hiBase, char* loBase,
                                           int r, int c4, float4 v) {
    __nv_bfloat16 h0 = __float2bfloat16_rn(v.x);
    __nv_bfloat16 h1 = __float2bfloat16_rn(v.y);
    __nv_bfloat16 h2 = __float2bfloat16_rn(v.z);
    __nv_bfloat16 h3 = __float2bfloat16_rn(v.w);
    __nv_bfloat16 l0 = __float2bfloat16_rn(v.x - __bfloat162float(h0));
    __nv_bfloat16 l1 = __float2bfloat16_rn(v.y - __bfloat162float(h1));
    __nv_bfloat16 l2 = __float2bfloat16_rn(v.z - __bfloat162float(h2));
    __nv_bfloat16 l3 = __float2bfloat16_rn(v.w - __bfloat162float(h3));
    uint32_t off = sw(r, c4 >> 1) + (c4 & 1) * 8;
    *(uint2*)(hiBase + off) = make_uint2(pack_bf16(h0, h1), pack_bf16(h2, h3));
    *(uint2*)(loBase + off) = make_uint2(pack_bf16(l0, l1), pack_bf16(l2, l3));
}

// ---------------------------------------------------------------------------
// prep: weight images (W1a^T, W1b^T, W1c^T hi/lo, swizzled) + silu table
// ---------------------------------------------------------------------------
extern "C" __global__ void k_prep(const float* __restrict__ W1)
{
    int idx = blockIdx.x * blockDim.x + threadIdx.x;
    if (idx < 24576) {
        int p   = idx >> 13;
        int rem = idx & 8191;
        int f   = rem >> 6;
        int k0  = (rem & 63) * 2;
        float v0 = W1[(p * 128 + k0) * FDIM + f];
        float v1 = W1[(p * 128 + k0 + 1) * FDIM + f];
        __nv_bfloat16 h0 = __float2bfloat16_rn(v0);
        __nv_bfloat16 h1 = __float2bfloat16_rn(v1);
        __nv_bfloat16 l0 = __float2bfloat16_rn(v0 - __bfloat162float(h0));
        __nv_bfloat16 l1 = __float2bfloat16_rn(v1 - __bfloat162float(h1));
        uint32_t off = sw(f, k0 >> 3) + (k0 & 7) * 2;
        *(uint32_t*)((char*)g_img[p][0] + off) = pack_bf16(h0, h1);
        *(uint32_t*)((char*)g_img[p][1] + off) = pack_bf16(l0, l1);
    } else if (idx < 24832) {
        int b = idx - 24576;
        float xc  = -8.0f + ((float)b + 0.5f) * 0.0625f;
        float s   = 1.0f / (1.0f + expf(-xc));
        float sp  = s * (1.0f - s);
        float spp = sp * (1.0f - 2.0f * s);
        g_tab[b] = make_float4(xc * s, s + xc * sp,
                               0.5f * (2.0f * sp + xc * spp), 0.0f);
    }
}

// ---------------------------------------------------------------------------
// precompute: g_A = x@W1a (warps 0-7), g_B = x@W1b (warps 8-15), M=128 tile
// smem: XHI 0, XLO 32768, imgs 65536..196608 ([a.hi a.lo b.hi b.lo] 32KB each)
// ---------------------------------------------------------------------------
#define PC_SMEM 196608

extern "C" __global__ void __launch_bounds__(512, 1)
k_precompute_tc(const float* __restrict__ x, int n_nodes)
{
    extern __shared__ char smem[];
    const uint32_t sb = smem_u32(smem);
    const int tid  = threadIdx.x;
    const int wid  = tid >> 5;
    const int lane = tid & 31;
    const int grow0 = blockIdx.x * 128;

    // copy all 4 weight images (128KB)
    {
        uint4* d0 = (uint4*)(smem + 65536);
        const uint4* s0 = (const uint4*)g_img[0][0];
        #pragma unroll
        for (int t = 0; t < 16; ++t) d0[t * 512 + tid] = s0[t * 512 + tid];
    }
    // convert x tile -> XHI/XLO
    #pragma unroll
    for (int it = 0; it < 8; ++it) {
        int idx = it * 512 + tid;
        int r = idx >> 5, c4 = idx & 31;
        int g = grow0 + r;
        float4 v = make_float4(0.f, 0.f, 0.f, 0.f);
        if (g < n_nodes) v = reinterpret_cast<const float4*>(x)[g * 32 + c4];
        cvt_store4(smem, smem + 32768, r, c4, v);
    }
    __syncthreads();

    const int part = wid >> 3;
    const int rb   = (wid & 7) * 16;
    const uint32_t xr   = lane & 7;
    const uint32_t aoff = sb + ((uint32_t)(rb + (lane & 15)) << 8);
    const uint32_t selA = lane >> 4;
    const uint32_t selB = (lane >> 3) & 1;
    const uint32_t bbase = sb + 65536 + (uint32_t)part * 65536;
    uint32_t browB[8];
    #pragma unroll
    for (int ntp = 0; ntp < 8; ++ntp)
        browB[ntp] = (uint32_t)(ntp * 16 + ((lane >> 4) & 1) * 8 + (lane & 7)) << 8;

    float acc[16][4];
    #pragma unroll
    for (int n = 0; n < 16; ++n)
        #pragma unroll
        for (int u = 0; u < 4; ++u) acc[n][u] = 0.f;

    #pragma unroll
    for (int k = 0; k < 8; ++k) {
        uint32_t ah[4], al[4];
        uint32_t ao = ((2 * k + selA) ^ xr) << 4;
        ldsm_x4(ah[0], ah[1], ah[2], ah[3], aoff + ao);
        ldsm_x4(al[0], al[1], al[2], al[3], aoff + 32768 + ao);
        uint32_t co = ((2 * k + selB) ^ xr) << 4;
        #pragma unroll
        for (int ntp = 0; ntp < 8; ++ntp) {
            uint32_t bh[4], bl[4];
            uint32_t ba = bbase + browB[ntp] + co;
            ldsm_x4(bh[0], bh[1], bh[2], bh[3], ba);
            ldsm_x4(bl[0], bl[1], bl[2], bl[3], ba + 32768);
            mma_bf16(acc[2 * ntp],     ah, bh[0], bh[1]);
            mma_bf16(acc[2 * ntp],     al, bh[0], bh[1]);
            mma_bf16(acc[2 * ntp],     ah, bl[0], bl[1]);
            mma_bf16(acc[2 * ntp + 1], ah, bh[2], bh[3]);
            mma_bf16(acc[2 * ntp + 1], al, bh[2], bh[3]);
            mma_bf16(acc[2 * ntp + 1], ah, bl[2], bl[3]);
        }
    }

    float* dst = part == 0 ? g_A : g_B;
    const int q  = lane >> 2;
    const int cL = (lane & 3) * 2;
    int g1 = grow0 + rb + q;
    int g2 = g1 + 8;
    #pragma unroll
    for (int nt = 0; nt < 16; ++nt) {
        int c = nt * 8 + cL;
        if (g1 < n_nodes) *(float2*)(dst + g1 * FDIM + c) = make_float2(acc[nt][0], acc[nt][1]);
        if (g2 < n_nodes) *(float2*)(dst + g2 * FDIM + c) = make_float2(acc[nt][2], acc[nt][3]);
    }
}

// ---------------------------------------------------------------------------
// pair kernel (persistent, M=256, 512 threads):
//   pre = w_tile @ W1c (3-pass split-bf16) ; out = silu_tab(pre+gA+gB+b1).W2+b2
// smem: BHI 0, BLO 32768, AHI 65536, ALO 131072 (A region reused as ADD tile),
//       TAB 200704, W2 204800, B1 205312, II 205824, JJ 206848
// ---------------------------------------------------------------------------
#define SO_BHI 0
#define SO_BLO 32768
#define SO_AHI 65536
#define SO_ALO 131072
#define SO_ADD 65536
#define ADD_STRIDE 132
#define SO_TAB 200704
#define SO_W2  204800
#define SO_B1  205312
#define SO_II  205824
#define SO_JJ  206848
#define KP_SMEM 207872

extern "C" __global__ void __launch_bounds__(512, 1)
k_pairs_tc(const float* __restrict__ w_ij,
           const float* __restrict__ b1,
           const float* __restrict__ W2,
           const float* __restrict__ b2,
           const int* __restrict__ idx_i,
           const int* __restrict__ idx_j,
           float* __restrict__ out,
           int n_pairs, int ntiles)
{
    extern __shared__ char smem[];
    const uint32_t sb = smem_u32(smem);
    const int tid  = threadIdx.x;
    const int wid  = tid >> 5;
    const int lane = tid & 31;

    float*  sAdd = (float*)(smem + SO_ADD);
    float4* sTab = (float4*)(smem + SO_TAB);
    float*  sW2  = (float*)(smem + SO_W2);
    float*  sB1  = (float*)(smem + SO_B1);
    int*    ii   = (int*)(smem + SO_II);
    int*    jj   = (int*)(smem + SO_JJ);

    // one-time: W1c hi/lo images (64KB), table, W2, b1
    {
        uint4* d0 = (uint4*)(smem + SO_BHI);
        const uint4* s0 = (const uint4*)g_img[2][0];
        #pragma unroll
        for (int t = 0; t < 8; ++t) d0[t * 512 + tid] = s0[t * 512 + tid];
        if (tid < 256) ((uint4*)sTab)[tid] = ((const uint4*)g_tab)[tid];
        if (tid < 32)  ((float4*)sW2)[tid] = ((const float4*)W2)[tid];
        else if (tid < 64) ((float4*)sB1)[tid - 32] = ((const float4*)b1)[tid - 32];
    }
    const float b2v = b2[0];

    const int rb = wid * 16;
    const uint32_t xr   = lane & 7;
    const uint32_t aoff = sb + SO_AHI + ((uint32_t)(rb + (lane & 15)) << 8);
    const uint32_t selA = lane >> 4;
    const uint32_t selB = (lane >> 3) & 1;
    uint32_t browB[8];
    #pragma unroll
    for (int ntp = 0; ntp < 8; ++ntp)
        browB[ntp] = (uint32_t)(ntp * 16 + ((lane >> 4) & 1) * 8 + (lane & 7)) << 8;
    const int q  = lane >> 2;
    const int cL = (lane & 3) * 2;

    for (int tile = blockIdx.x; tile < ntiles; tile += gridDim.x) {
        const int p0 = tile * 256;

        // phase 1: convert w_ij tile -> A hi/lo images; stage indices
        #pragma unroll
        for (int it = 0; it < 16; ++it) {
            int idx = it * 512 + tid;
            int r = idx >> 5, c4 = idx & 31;
            int gp = p0 + r;
            float4 v = make_float4(0.f, 0.f, 0.f, 0.f);
            if (gp < n_pairs) v = reinterpret_cast<const float4*>(w_ij)[gp * 32 + c4];
            cvt_store4(smem + SO_AHI, smem + SO_ALO, r, c4, v);
        }
        {
            int gp = p0 + (tid & 255);
            gp = gp < n_pairs ? gp : 0;
            if (tid < 256) ii[tid] = __ldg(idx_i + gp);
            else           jj[tid - 256] = __ldg(idx_j + gp);
        }
        __syncthreads();

        // phase 2: MMA (3-pass split bf16), rows rb..rb+15 per warp
        float acc[16][4];
        #pragma unroll
        for (int n = 0; n < 16; ++n)
            #pragma unroll
            for (int u = 0; u < 4; ++u) acc[n][u] = 0.f;

        #pragma unroll
        for (int k = 0; k < 8; ++k) {
            uint32_t ah[4], al[4];
            uint32_t ao = ((2 * k + selA) ^ xr) << 4;
            ldsm_x4(ah[0], ah[1], ah[2], ah[3], aoff + ao);
            ldsm_x4(al[0], al[1], al[2], al[3], aoff + 65536 + ao);
            uint32_t co = ((2 * k + selB) ^ xr) << 4;
            #pragma unroll
            for (int ntp = 0; ntp < 8; ++ntp) {
                uint32_t bh[4], bl[4];
                uint32_t ba = sb + SO_BHI + browB[ntp] + co;
                ldsm_x4(bh[0], bh[1], bh[2], bh[3], ba);
                ldsm_x4(bl[0], bl[1], bl[2], bl[3], ba + 32768);
                mma_bf16(acc[2 * ntp],     ah, bh[0], bh[1]);
                mma_bf16(acc[2 * ntp],     al, bh[0], bh[1]);
                mma_bf16(acc[2 * ntp],     ah, bl[0], bl[1]);
                mma_bf16(acc[2 * ntp + 1], ah, bh[2], bh[3]);
                mma_bf16(acc[2 * ntp + 1], al, bh[2], bh[3]);
                mma_bf16(acc[2 * ntp + 1], ah, bl[2], bl[3]);
            }
        }
        __syncthreads();   // A images fully consumed -> region reusable

        // phase 3: gather addend tile (gA[ii] + gB[jj] + b1) into ADD region
        #pragma unroll
        for (int it = 0; it < 16; ++it) {
            int idx = it * 512 + tid;
            int r = idx >> 5, c4 = idx & 31;
            int ri = ii[r], rj = jj[r];
            float4 va = reinterpret_cast<const float4*>(g_A)[ri * 32 + c4];
            float4 vb = reinterpret_cast<const float4*>(g_B)[rj * 32 + c4];
            float4 v1 = *(const float4*)(sB1 + c4 * 4);
            *(float4*)(sAdd + r * ADD_STRIDE + c4 * 4) =
                make_float4(va.x + vb.x + v1.x, va.y + vb.y + v1.y,
                            va.z + vb.z + v1.z, va.w + vb.w + v1.w);
        }
        __syncthreads();

        // phase 4: fused epilogue (table silu + W2 dot)
        const int r1 = rb + q;
        const int r2 = r1 + 8;
        float sum1 = 0.f, sum2 = 0.f;
        #pragma unroll
        for (int nt = 0; nt < 16; ++nt) {
            int c = nt * 8 + cL;
            float2 w2 = *(float2*)(sW2 + c);
            float2 a1 = *(float2*)(sAdd + r1 * ADD_STRIDE + c);
            float2 a2 = *(float2*)(sAdd + r2 * ADD_STRIDE + c);
            float vv[4] = { acc[nt][0] + a1.x, acc[nt][1] + a1.y,
                            acc[nt][2] + a2.x, acc[nt][3] + a2.y };
            float ss[4];
            #pragma unroll
            for (int u = 0; u < 4; ++u) {
                float t  = fminf(fmaxf(vv[u], -7.999f), 7.999f);
                int   ib = (int)((t + 8.0f) * 16.0f);
                float xc = fmaf((float)ib, 0.0625f, -7.96875f);
                float dv = t - xc;
                float4 cc = sTab[ib];
                ss[u] = fmaf(fmaf(cc.z, dv, cc.y), dv, cc.x);
            }
            sum1 = fmaf(ss[0], w2.x, fmaf(ss[1], w2.y, sum1));
            sum2 = fmaf(ss[2], w2.x, fmaf(ss[3], w2.y, sum2));
        }
        sum1 += __shfl_xor_sync(0xffffffff, sum1, 1);
        sum1 += __shfl_xor_sync(0xffffffff, sum1, 2);
        sum2 += __shfl_xor_sync(0xffffffff, sum2, 1);
        sum2 += __shfl_xor_sync(0xffffffff, sum2, 2);
        if ((lane & 3) == 0) {
            int g1 = p0 + r1, g2 = p0 + r2;
            if (g1 < n_pairs) out[g1] = sum1 + b2v;
            if (g2 < n_pairs) out[g2] = sum2 + b2v;
        }
        __syncthreads();   // ADD region reused as A images next tile
    }
}

// ---------------------------------------------------------------------------
extern "C" void kernel_launch(void* const* d_in, const int* in_sizes, int n_in,
                              void* d_out, int out_size)
{
    const float* x     = (const float*)d_in[0];
    const float* w_ij  = (const float*)d_in[1];
    const float* W1    = (const float*)d_in[2];
    const float* b1    = (const float*)d_in[3];
    const float* W2    = (const float*)d_in[4];
    const float* b2    = (const float*)d_in[5];
    const int*   idx_i = (const int*)d_in[6];
    const int*   idx_j = (const int*)d_in[7];
    float* out = (float*)d_out;

    const int n_nodes = in_sizes[0] / FDIM;
    const int n_pairs = out_size;
    const int ntiles  = (n_pairs + 255) / 256;

    cudaFuncSetAttribute(k_precompute_tc, cudaFuncAttributeMaxDynamicSharedMemorySize, PC_SMEM);
    cudaFuncSetAttribute(k_pairs_tc,      cudaFuncAttributeMaxDynamicSharedMemorySize, KP_SMEM);

    int nsm = 148;
    cudaDeviceGetAttribute(&nsm, cudaDevAttrMultiProcessorCount, 0);
    if (nsm <= 0) nsm = 148;
    int grid2 = nsm < ntiles ? nsm : ntiles;

    k_prep<<<97, 256>>>(W1);
    k_precompute_tc<<<(n_nodes + 127) / 128, 512, PC_SMEM>>>(x, n_nodes);
    k_pairs_tc<<<grid2, 512, KP_SMEM>>>(w_ij, b1, W2, b2, idx_i, idx_j,
                                        out, n_pairs, ntiles);
}